// round 14
// baseline (speedup 1.0000x reference)
#include <cuda_runtime.h>
#include <cuda_fp16.h>
#include <cstdint>

// ---------------- problem constants ----------------
#define BATCH 512
#define EDIM  128
#define NCOLS 640
#define EPS   1e-5f

// split-K: 74 slices, 4 m-tiles of 128 rows -> 296 CTAs (2 per SM)
#define NSL_KW 52
#define NSL_FO 3
#define NSL_AU 3
#define NSL_MG 4
#define NSL_TG 12
#define NSL_TOT (NSL_KW + NSL_FO + NSL_AU + NSL_MG + NSL_TG)   // 74

#define CH 96                  // K elements per chunk (three 32-k halves)
#define HALF_A 8192            // bytes per A sub-tile (128 rows x 32 k fp16)
#define OFS_W  24576           // W region offset within stage (3 x 8K A first)
#define STAGE  49152           // [A0 A1 A2 | W0 W1 W2] x 8K
#define SMEM_DYN (2 * STAGE + 128)

// ---------------- device scratch ----------------
__device__ float g_part[(long)NSL_TOT * BATCH * EDIM];   // ~19.4 MB
__device__ float g_emb[BATCH * NCOLS];
__device__ float g_scale[NCOLS];
__device__ float g_shift[NCOLS];
__device__ float g_hu[BATCH * EDIM];
__device__ float g_ue[BATCH * EDIM];
__device__ float g_hi_[BATCH * EDIM];
__device__ float g_ie[BATCH * EDIM];

// ---------------- helpers ----------------
__device__ __forceinline__ uint32_t smem_u32(const void* p) {
    uint32_t a;
    asm("{ .reg .u64 t; cvta.to.shared.u64 t, %1; cvt.u32.u64 %0, t; }" : "=r"(a) : "l"(p));
    return a;
}

// swizzled byte offset within an 8KB sub-tile: row r (64B wide), 16B chunk c (0..3)
__device__ __forceinline__ uint32_t swz(int r, int c) {
    return (uint32_t)r * 64u + (uint32_t)((c ^ ((r >> 1) & 3)) << 4);
}

#define LDX4(r, addr) \
    asm volatile("ldmatrix.sync.aligned.m8n8.x4.shared.b16 {%0,%1,%2,%3}, [%4];" \
        : "=r"((r)[0]), "=r"((r)[1]), "=r"((r)[2]), "=r"((r)[3]) : "r"(addr))

#define MMAF16(c, a, b) \
    asm volatile("mma.sync.aligned.m16n8k16.row.col.f32.f16.f16.f32 " \
        "{%0,%1,%2,%3}, {%4,%5,%6,%7}, {%8,%9}, {%0,%1,%2,%3};" \
        : "+f"((c)[0]), "+f"((c)[1]), "+f"((c)[2]), "+f"((c)[3]) \
        : "r"((a)[0]), "r"((a)[1]), "r"((a)[2]), "r"((a)[3]), \
          "r"((b)[0]), "r"((b)[1]))

#define STS128(addr, r) \
    asm volatile("st.shared.v4.b32 [%0], {%1,%2,%3,%4};" \
        :: "r"(addr), "r"((r)[0]), "r"((r)[1]), "r"((r)[2]), "r"((r)[3]) : "memory")

// 8 floats -> 4x fp16x2
__device__ __forceinline__ void cvt8(const float* x, uint32_t* hi) {
    #pragma unroll
    for (int q = 0; q < 4; q++) {
        __half2 h = __floats2half2_rn(x[2 * q], x[2 * q + 1]);
        hi[q] = *reinterpret_cast<uint32_t*>(&h);
    }
}

struct BigParams {
    const float* A[5];
    const float* W[5];
    int K[5];
    int kc[5];
    int cum[6];
};
struct RedParams {
    const float* bias[5];
    int cum[6];
    int col_ofs[5];
};
struct TowerParams {
    const float* W[2];
    const float* bias[2];
};

// ================= fp16 mma.sync big GEMM, 2 CTAs/SM, CH=96 =================
// CTA: 128 rows x one K-slice. 8 warps, warp tile 32m x 64n.
__global__ __launch_bounds__(256, 2) void big_gemm_kernel(BigParams p) {
    extern __shared__ __align__(128) char dyn_smem[];
    const uint32_t sBase = (smem_u32(dyn_smem) + 127u) & ~127u;

    const int t    = threadIdx.x;
    const int lane = t & 31;
    const int w    = t >> 5;

    const int sidx   = blockIdx.x >> 2;
    const int m_base = (blockIdx.x & 3) * 128;

    int g = 0;
    while (sidx >= p.cum[g + 1]) g++;
    const int s_loc = sidx - p.cum[g];
    const float* __restrict__ A = p.A[g];
    const float* __restrict__ W = p.W[g];
    const int K  = p.K[g];
    const int k0 = s_loc * p.kc[g];
    const int k1 = min(k0 + p.kc[g], K);
    const int nchunks = (k1 - k0 + CH - 1) / CH;
    const int kmode = ((K & 3) == 0) ? 2 : (((K & 1) == 0) ? 1 : 0);

    const int lr  = t >> 2;      // 0..63
    const int lc  = t & 3;
    float aBuf[2][8], wBuf[2][8];

    const int wm = w >> 1;
    const int wn = w & 1;
    const int aR = wm * 32 + (lane & 15);
    const int bR = wn * 64 + ((lane >> 4) & 1) * 8 + (lane & 7);
    const int aCsel = (lane >> 4);        // 0/1
    const int bCsel = ((lane >> 3) & 1);  // 0/1

    float acc[2][4][2][4];
    #pragma unroll
    for (int mi = 0; mi < 2; mi++)
        #pragma unroll
        for (int np = 0; np < 4; np++)
            #pragma unroll
            for (int nt = 0; nt < 2; nt++)
                #pragma unroll
                for (int r = 0; r < 4; r++) acc[mi][np][nt][r] = 0.f;

    #define LOAD8(dst, P, gi, kk)                                             \
    do {                                                                      \
        if (full) {                                                           \
            if (kmode == 2) {                                                 \
                float4 v0 = *(const float4*)&P[gi];                           \
                float4 v1 = *(const float4*)&P[gi + 4];                       \
                dst[0]=v0.x; dst[1]=v0.y; dst[2]=v0.z; dst[3]=v0.w;           \
                dst[4]=v1.x; dst[5]=v1.y; dst[6]=v1.z; dst[7]=v1.w;           \
            } else if (kmode == 1) {                                          \
                _Pragma("unroll")                                             \
                for (int q = 0; q < 4; q++) {                                 \
                    float2 v = *(const float2*)&P[gi + 2 * q];                \
                    dst[2 * q] = v.x; dst[2 * q + 1] = v.y;                   \
                }                                                             \
            } else {                                                          \
                _Pragma("unroll")                                             \
                for (int q = 0; q < 8; q++) dst[q] = P[gi + q];               \
            }                                                                 \
        } else {                                                              \
            _Pragma("unroll")                                                 \
            for (int q = 0; q < 8; q++)                                       \
                dst[q] = (kk + q < k1) ? P[gi + q] : 0.f;                     \
        }                                                                     \
    } while (0)

    // load one 32-k sub-tile of chunk IDX into regs
    #define LOAD_HALF(IDX, H)                                                 \
    do {                                                                      \
        const int kb = k0 + (IDX) * CH + (H) * 32;                            \
        const bool full = (kb + 32 <= k1);                                    \
        const int kk = kb + lc * 8;                                           \
        { long gi = (long)(m_base + lr) * K + kk;      LOAD8(aBuf[0], A, gi, kk); } \
        { long gi = (long)(m_base + 64 + lr) * K + kk; LOAD8(aBuf[1], A, gi, kk); } \
        { long gi = (long)lr * K + kk;                 LOAD8(wBuf[0], W, gi, kk); } \
        { long gi = (long)(64 + lr) * K + kk;          LOAD8(wBuf[1], W, gi, kk); } \
    } while (0)

    #define STS_HALF(SO, H)                                                   \
    do {                                                                      \
        const uint32_t ab = sBase + (SO) + (uint32_t)(H) * HALF_A;            \
        uint32_t hi[4];                                                       \
        uint32_t off0 = swz(lr, lc);                                          \
        uint32_t off1 = swz(64 + lr, lc);                                     \
        cvt8(aBuf[0], hi);  STS128(ab + off0, hi);                            \
        cvt8(aBuf[1], hi);  STS128(ab + off1, hi);                            \
        cvt8(wBuf[0], hi);  STS128(ab + OFS_W + off0, hi);                    \
        cvt8(wBuf[1], hi);  STS128(ab + OFS_W + off1, hi);                    \
    } while (0)

    #define MMA_HALF(SO, H)                                                   \
    do {                                                                      \
        const uint32_t so_a = sBase + (SO) + (uint32_t)(H) * HALF_A;          \
        const uint32_t so_w = so_a + OFS_W;                                   \
        _Pragma("unroll")                                                     \
        for (int ks = 0; ks < 2; ks++) {                                      \
            uint32_t AH[2][4];                                                \
            _Pragma("unroll")                                                 \
            for (int mi = 0; mi < 2; mi++) {                                  \
                int r = aR + mi * 16;                                         \
                LDX4(AH[mi], so_a + swz(r, ks * 2 + aCsel));                  \
            }                                                                 \
            _Pragma("unroll")                                                 \
            for (int np = 0; np < 4; np++) {                                  \
                int r = bR + np * 16;                                         \
                uint32_t BH[4];                                               \
                LDX4(BH, so_w + swz(r, ks * 2 + bCsel));                      \
                _Pragma("unroll")                                             \
                for (int mi = 0; mi < 2; mi++) {                              \
                    _Pragma("unroll")                                         \
                    for (int nt = 0; nt < 2; nt++) {                          \
                        MMAF16(acc[mi][np][nt], AH[mi], BH + 2 * nt);         \
                    }                                                         \
                }                                                             \
            }                                                                 \
        }                                                                     \
    } while (0)

    // prologue: chunk 0 into stage 0
    LOAD_HALF(0, 0);
    STS_HALF(0, 0);
    LOAD_HALF(0, 1);
    STS_HALF(0, 1);
    LOAD_HALF(0, 2);
    STS_HALF(0, 2);
    __syncthreads();

    for (int i = 0; i < nchunks; i++) {
        const bool more = (i + 1 < nchunks);
        const uint32_t so  = (uint32_t)(i & 1) * STAGE;
        const uint32_t son = (uint32_t)((i + 1) & 1) * STAGE;

        if (more) LOAD_HALF(i + 1, 0);
        MMA_HALF(so, 0);
        if (more) {
            STS_HALF(son, 0);
            LOAD_HALF(i + 1, 1);
        }
        MMA_HALF(so, 1);
        if (more) {
            STS_HALF(son, 1);
            LOAD_HALF(i + 1, 2);
        }
        MMA_HALF(so, 2);
        if (more) STS_HALF(son, 2);
        __syncthreads();
    }

    // epilogue
    #pragma unroll
    for (int mi = 0; mi < 2; mi++) {
        #pragma unroll
        for (int np = 0; np < 4; np++) {
            #pragma unroll
            for (int nt = 0; nt < 2; nt++) {
                int m = m_base + wm * 32 + mi * 16 + (lane >> 2);
                int n = wn * 64 + np * 16 + nt * 8 + (lane & 3) * 2;
                float* o = g_part + ((long)sidx * BATCH + m) * EDIM + n;
                *(float2*)o = make_float2(acc[mi][np][nt][0], acc[mi][np][nt][1]);
                *(float2*)(o + 8 * EDIM) = make_float2(acc[mi][np][nt][2], acc[mi][np][nt][3]);
            }
        }
    }
}

// ================= reduce split-K partials + bias =================
__global__ void reduce_kernel(RedParams p) {
    int g   = blockIdx.y;
    int idx = blockIdx.x * blockDim.x + threadIdx.x;
    int b   = idx >> 7;
    int j   = idx & 127;
    float v = p.bias[g][j];
    int s0 = p.cum[g], s1 = p.cum[g + 1];
    for (int s = s0; s < s1; s++)
        v += g_part[(long)s * (BATCH * EDIM) + idx];
    g_emb[b * NCOLS + p.col_ofs[g] + j] = v;
}

// ================= BN stats (coalesced) =================
__global__ void stats_kernel(const float* g_u, const float* be_u,
                             const float* g_i, const float* be_i) {
    __shared__ float ss[8][32], sq[8][32];
    int lane = threadIdx.x & 31;
    int ty   = threadIdx.x >> 5;
    int c = blockIdx.x * 32 + lane;
    float s = 0.f, q = 0.f;
    for (int b = ty; b < BATCH; b += 8) {
        float x = g_emb[b * NCOLS + c];
        s += x; q += x * x;
    }
    ss[ty][lane] = s; sq[ty][lane] = q;
    __syncthreads();
    if (ty == 0) {
        #pragma unroll
        for (int r = 1; r < 8; r++) { s += ss[r][lane]; q += sq[r][lane]; }
        float mean = s * (1.f / BATCH);
        float var  = q * (1.f / BATCH) - mean * mean;
        float gamma = (c < 256) ? g_u[c]  : g_i[c - 256];
        float beta  = (c < 256) ? be_u[c] : be_i[c - 256];
        float sc = gamma * rsqrtf(var + EPS);
        g_scale[c] = sc;
        g_shift[c] = beta - mean * sc;
    }
}

// ================= tower layer 1: j-split, grid 256 =================
// CTA: 8 rows x 64 output cols. warp = 1 row, 2 cols per lane.
#define WS_PITCH 66
__global__ __launch_bounds__(256) void tower1_kernel(TowerParams p) {
    __shared__ float As[8 * 384];
    __shared__ float Ws[2][32 * WS_PITCH];

    int which = blockIdx.x >> 7;          // 0 = user, 1 = item
    int rest  = blockIdx.x & 127;
    int blk   = rest >> 1;                // 0..63 row block
    int jh    = rest & 1;                 // 0/1 col half
    int K     = which ? 384 : 256;
    int a_ofs = which ? 256 : 0;
    int jbase = jh * 64;
    const float* __restrict__ W    = p.W[which];
    const float* __restrict__ bias = p.bias[which];
    float* C = which ? g_hi_ : g_hu;

    int t    = threadIdx.x;
    int lane = t & 31;
    int w    = t >> 5;
    int m0   = blk * 8;

    const int jw = t >> 2;        // 0..63 (local j)
    const int kh = (t & 3) * 8;   // 0,8,16,24
    const int ntiles = K / 32;

    float wreg[8];
    // prefetch W tile 0 (hide under As gather)
    {
        const float* wr = &W[(jbase + jw) * K + kh];
        float4 v0 = *(const float4*)&wr[0];
        float4 v1 = *(const float4*)&wr[4];
        wreg[0]=v0.x; wreg[1]=v0.y; wreg[2]=v0.z; wreg[3]=v0.w;
        wreg[4]=v1.x; wreg[5]=v1.y; wreg[6]=v1.z; wreg[7]=v1.w;
    }

    for (int e = t; e < 8 * K; e += 256) {
        int r = e / K, c = e - r * K;
        float v = g_emb[(m0 + r) * NCOLS + a_ofs + c];
        As[e] = fmaf(v, g_scale[a_ofs + c], g_shift[a_ofs + c]);
    }

    #pragma unroll
    for (int q = 0; q < 8; q++) Ws[0][(kh + q) * WS_PITCH + jw] = wreg[q];
    __syncthreads();

    const int r = w;              // warp = row
    float acc[2];
    acc[0] = bias[jbase + lane * 2];
    acc[1] = bias[jbase + lane * 2 + 1];

    for (int i = 0; i < ntiles; i++) {
        const bool more = (i + 1 < ntiles);
        if (more) {
            const float* wr = &W[(jbase + jw) * K + (i + 1) * 32 + kh];
            float4 v0 = *(const float4*)&wr[0];
            float4 v1 = *(const float4*)&wr[4];
            wreg[0]=v0.x; wreg[1]=v0.y; wreg[2]=v0.z; wreg[3]=v0.w;
            wreg[4]=v1.x; wreg[5]=v1.y; wreg[6]=v1.z; wreg[7]=v1.w;
        }
        const float* wsb = Ws[i & 1];
        const int kb = i * 32;
        #pragma unroll 8
        for (int kk = 0; kk < 32; kk++) {
            float a = As[r * K + kb + kk];
            float2 wv = *(const float2*)&wsb[kk * WS_PITCH + lane * 2];
            acc[0] = fmaf(a, wv.x, acc[0]);
            acc[1] = fmaf(a, wv.y, acc[1]);
        }
        if (more) {
            #pragma unroll
            for (int q = 0; q < 8; q++)
                Ws[(i + 1) & 1][(kh + q) * WS_PITCH + jw] = wreg[q];
            __syncthreads();
        }
    }

    float2 v;
    v.x = fmaxf(acc[0], 0.f);
    v.y = fmaxf(acc[1], 0.f);
    *(float2*)&C[(m0 + r) * EDIM + jbase + lane * 2] = v;
}

// ================= tower layer 2 (user + item), W double-buffered =====
__global__ __launch_bounds__(256) void tower2_kernel(TowerParams p) {
    __shared__ float As[8 * 128];
    __shared__ float Ws[2][32 * 128];

    int which = blockIdx.x >> 6;
    int blk   = blockIdx.x & 63;
    const int K = 128;
    const float* __restrict__ A    = which ? g_hi_ : g_hu;
    const float* __restrict__ W    = p.W[which];
    const float* __restrict__ bias = p.bias[which];
    float* C = which ? g_ie : g_ue;

    int t  = threadIdx.x;
    int m0 = blk * 8;

    for (int e = t; e < 8 * K; e += 256) As[e] = A[m0 * K + e];

    int r  = t >> 5;
    int j0 = (t & 31) * 4;
    float acc[4];
    #pragma unroll
    for (int j = 0; j < 4; j++) acc[j] = bias[j0 + j];

    const int jw = t >> 1;
    const int kh = (t & 1) * 16;
    const int ntiles = K / 32;

    float wreg[16];
    #pragma unroll
    for (int q = 0; q < 4; q++) {
        float4 v = *(const float4*)&W[jw * K + kh + q * 4];
        wreg[q * 4 + 0] = v.x; wreg[q * 4 + 1] = v.y;
        wreg[q * 4 + 2] = v.z; wreg[q * 4 + 3] = v.w;
    }
    #pragma unroll
    for (int q = 0; q < 16; q++) Ws[0][(kh + q) * 128 + jw] = wreg[q];
    __syncthreads();

    for (int i = 0; i < ntiles; i++) {
        const bool more = (i + 1 < ntiles);
        if (more) {
            int kb = (i + 1) * 32;
            #pragma unroll
            for (int q = 0; q < 4; q++) {
                float4 v = *(const float4*)&W[jw * K + kb + kh + q * 4];
                wreg[q * 4 + 0] = v.x; wreg[q * 4 + 1] = v.y;
                wreg[q * 4 + 2] = v.z; wreg[q * 4 + 3] = v.w;
            }
        }
        const float* wsb = Ws[i & 1];
        const int kb = i * 32;
        #pragma unroll 8
        for (int kk = 0; kk < 32; kk++) {
            float a = As[r * K + kb + kk];
            float4 wv = *(const float4*)&wsb[kk * 128 + j0];
            acc[0] = fmaf(a, wv.x, acc[0]);
            acc[1] = fmaf(a, wv.y, acc[1]);
            acc[2] = fmaf(a, wv.z, acc[2]);
            acc[3] = fmaf(a, wv.w, acc[3]);
        }
        if (more) {
            #pragma unroll
            for (int q = 0; q < 16; q++)
                Ws[(i + 1) & 1][(kh + q) * 128 + jw] = wreg[q];
            __syncthreads();
        }
    }

    *(float4*)&C[(m0 + r) * EDIM + j0] =
        make_float4(acc[0], acc[1], acc[2], acc[3]);
}

// ================= final dot =================
__global__ void dot_kernel(float* __restrict__ out) {
    int warp = threadIdx.x >> 5;
    int lane = threadIdx.x & 31;
    int b = blockIdx.x * 8 + warp;
    float s = 0.f;
    #pragma unroll
    for (int j = lane; j < EDIM; j += 32)
        s += g_ue[b * EDIM + j] * g_ie[b * EDIM + j];
    #pragma unroll
    for (int o = 16; o > 0; o >>= 1)
        s += __shfl_xor_sync(0xffffffffu, s, o);
    if (lane == 0) out[b] = s;
}

// ================= launch =================
extern "C" void kernel_launch(void* const* d_in, const int* in_sizes, int n_in,
                              void* d_out, int out_size) {
    const float* kw   = (const float*)d_in[0];
    const float* fo   = (const float*)d_in[1];
    const float* au   = (const float*)d_in[2];
    const float* mg   = (const float*)d_in[3];
    const float* tg   = (const float*)d_in[4];
    const float* W_kw = (const float*)d_in[5];
    const float* b_kw = (const float*)d_in[6];
    const float* W_au = (const float*)d_in[7];
    const float* b_au = (const float*)d_in[8];
    const float* W_mg = (const float*)d_in[9];
    const float* b_mg = (const float*)d_in[10];
    const float* W_tg = (const float*)d_in[11];
    const float* b_tg = (const float*)d_in[12];
    const float* g_u  = (const float*)d_in[13];
    const float* be_u = (const float*)d_in[14];
    const float* W_u1 = (const float*)d_in[15];
    const float* b_u1 = (const float*)d_in[16];
    const float* W_u2 = (const float*)d_in[17];
    const float* b_u2 = (const float*)d_in[18];
    const float* g_i  = (const float*)d_in[19];
    const float* be_i = (const float*)d_in[20];
    const float* W_i1 = (const float*)d_in[21];
    const float* b_i1 = (const float*)d_in[22];
    const float* W_i2 = (const float*)d_in[23];
    const float* b_i2 = (const float*)d_in[24];

    const int KW = 372226, AU = 19065, MG = 28028, TG = 86037;

    BigParams bp;
    bp.A[0] = kw;  bp.A[1] = fo;  bp.A[2] = au;  bp.A[3] = mg;  bp.A[4] = tg;
    bp.W[0] = W_kw; bp.W[1] = W_au; bp.W[2] = W_au; bp.W[3] = W_mg; bp.W[4] = W_tg;
    bp.K[0] = KW;  bp.K[1] = AU;  bp.K[2] = AU;  bp.K[3] = MG;  bp.K[4] = TG;
    // K per slice (multiple of 96), count*kc >= K
    bp.kc[0] = 7200;   // 52*7200 = 374400 >= 372226
    bp.kc[1] = 6432;   // 3*6432  = 19296  >= 19065
    bp.kc[2] = 6432;
    bp.kc[3] = 7104;   // 4*7104  = 28416  >= 28028
    bp.kc[4] = 7200;   // 12*7200 = 86400  >= 86037
    bp.cum[0] = 0;
    bp.cum[1] = NSL_KW;
    bp.cum[2] = NSL_KW + NSL_FO;
    bp.cum[3] = NSL_KW + NSL_FO + NSL_AU;
    bp.cum[4] = NSL_KW + NSL_FO + NSL_AU + NSL_MG;
    bp.cum[5] = NSL_TOT;

    RedParams rp;
    rp.bias[0] = b_kw; rp.bias[1] = b_au; rp.bias[2] = b_au;
    rp.bias[3] = b_mg; rp.bias[4] = b_tg;
    for (int i = 0; i < 6; i++) rp.cum[i] = bp.cum[i];
    rp.col_ofs[0] = 0;   rp.col_ofs[1] = 128; rp.col_ofs[2] = 256;
    rp.col_ofs[3] = 384; rp.col_ofs[4] = 512;

    TowerParams t1;
    t1.W[0] = W_u1; t1.W[1] = W_i1;
    t1.bias[0] = b_u1; t1.bias[1] = b_i1;
    TowerParams t2;
    t2.W[0] = W_u2; t2.W[1] = W_i2;
    t2.bias[0] = b_u2; t2.bias[1] = b_i2;

    cudaFuncSetAttribute(big_gemm_kernel,
                         cudaFuncAttributeMaxDynamicSharedMemorySize, SMEM_DYN);

    big_gemm_kernel<<<NSL_TOT * 4, 256, SMEM_DYN>>>(bp);
    reduce_kernel<<<dim3((BATCH * EDIM) / 256, 5), 256>>>(rp);
    stats_kernel<<<NCOLS / 32, 256>>>(g_u, be_u, g_i, be_i);
    tower1_kernel<<<256, 256>>>(t1);
    tower2_kernel<<<128, 256>>>(t2);
    dot_kernel<<<BATCH / 8, 256>>>((float*)d_out);
}

// round 15
// speedup vs baseline: 1.2549x; 1.2549x over previous
#include <cuda_runtime.h>
#include <cuda_fp16.h>
#include <cstdint>

// ---------------- problem constants ----------------
#define BATCH 512
#define EDIM  128
#define NCOLS 640
#define EPS   1e-5f

// split-K: 74 slices, 4 m-tiles of 128 rows -> 296 CTAs (2 per SM)
#define NSL_KW 52
#define NSL_FO 3
#define NSL_AU 3
#define NSL_MG 4
#define NSL_TG 12
#define NSL_TOT (NSL_KW + NSL_FO + NSL_AU + NSL_MG + NSL_TG)   // 74

#define CH 64                  // K elements per chunk (two 32-k halves)
#define HALF_A 8192            // bytes per A half tile (128 rows x 32 k fp16)
#define OFS_W  16384           // W region offset within stage
#define STAGE  32768           // [A0 8K | A1 8K | W0 8K | W1 8K]
#define SMEM_DYN (2 * STAGE + 128)

// ---------------- device scratch ----------------
__device__ float g_part[(long)NSL_TOT * BATCH * EDIM];   // ~19.4 MB
__device__ float g_emb[BATCH * NCOLS];
__device__ float g_scale[NCOLS];
__device__ float g_shift[NCOLS];
__device__ float g_hu[BATCH * EDIM];
__device__ float g_ue[BATCH * EDIM];
__device__ float g_hi_[BATCH * EDIM];
__device__ float g_ie[BATCH * EDIM];

// ---------------- helpers ----------------
__device__ __forceinline__ uint32_t smem_u32(const void* p) {
    uint32_t a;
    asm("{ .reg .u64 t; cvta.to.shared.u64 t, %1; cvt.u32.u64 %0, t; }" : "=r"(a) : "l"(p));
    return a;
}

// swizzled byte offset within an 8KB sub-tile: row r (64B wide), 16B chunk c (0..3)
__device__ __forceinline__ uint32_t swz(int r, int c) {
    return (uint32_t)r * 64u + (uint32_t)((c ^ ((r >> 1) & 3)) << 4);
}

#define LDX4(r, addr) \
    asm volatile("ldmatrix.sync.aligned.m8n8.x4.shared.b16 {%0,%1,%2,%3}, [%4];" \
        : "=r"((r)[0]), "=r"((r)[1]), "=r"((r)[2]), "=r"((r)[3]) : "r"(addr))

#define MMAF16(c, a, b) \
    asm volatile("mma.sync.aligned.m16n8k16.row.col.f32.f16.f16.f32 " \
        "{%0,%1,%2,%3}, {%4,%5,%6,%7}, {%8,%9}, {%0,%1,%2,%3};" \
        : "+f"((c)[0]), "+f"((c)[1]), "+f"((c)[2]), "+f"((c)[3]) \
        : "r"((a)[0]), "r"((a)[1]), "r"((a)[2]), "r"((a)[3]), \
          "r"((b)[0]), "r"((b)[1]))

#define STS128(addr, r) \
    asm volatile("st.shared.v4.b32 [%0], {%1,%2,%3,%4};" \
        :: "r"(addr), "r"((r)[0]), "r"((r)[1]), "r"((r)[2]), "r"((r)[3]) : "memory")

// 8 floats -> 4x fp16x2
__device__ __forceinline__ void cvt8(const float* x, uint32_t* hi) {
    #pragma unroll
    for (int q = 0; q < 4; q++) {
        __half2 h = __floats2half2_rn(x[2 * q], x[2 * q + 1]);
        hi[q] = *reinterpret_cast<uint32_t*>(&h);
    }
}

struct BigParams {
    const float* A[5];
    const float* W[5];
    int K[5];
    int kc[5];
    int cum[6];
};
struct RedParams {
    const float* bias[5];
    int cum[6];
    int col_ofs[5];
};
struct TowerParams {
    const float* W[2];
    const float* bias[2];
};

// ================= fp16 mma.sync big GEMM, 2 CTAs/SM, CH=64 (R13) =================
// CTA: 128 rows x one K-slice. 8 warps, warp tile 32m x 64n.
__global__ __launch_bounds__(256, 2) void big_gemm_kernel(BigParams p) {
    extern __shared__ __align__(128) char dyn_smem[];
    const uint32_t sBase = (smem_u32(dyn_smem) + 127u) & ~127u;

    const int t    = threadIdx.x;
    const int lane = t & 31;
    const int w    = t >> 5;

    const int sidx   = blockIdx.x >> 2;
    const int m_base = (blockIdx.x & 3) * 128;

    int g = 0;
    while (sidx >= p.cum[g + 1]) g++;
    const int s_loc = sidx - p.cum[g];
    const float* __restrict__ A = p.A[g];
    const float* __restrict__ W = p.W[g];
    const int K  = p.K[g];
    const int k0 = s_loc * p.kc[g];
    const int k1 = min(k0 + p.kc[g], K);
    const int nchunks = (k1 - k0 + CH - 1) / CH;
    const int kmode = ((K & 3) == 0) ? 2 : (((K & 1) == 0) ? 1 : 0);

    const int lr  = t >> 2;      // 0..63
    const int lc  = t & 3;
    float aBuf[2][8], wBuf[2][8];

    const int wm = w >> 1;
    const int wn = w & 1;
    const int aR = wm * 32 + (lane & 15);
    const int bR = wn * 64 + ((lane >> 4) & 1) * 8 + (lane & 7);
    const int aCsel = (lane >> 4);        // 0/1
    const int bCsel = ((lane >> 3) & 1);  // 0/1

    float acc[2][4][2][4];
    #pragma unroll
    for (int mi = 0; mi < 2; mi++)
        #pragma unroll
        for (int np = 0; np < 4; np++)
            #pragma unroll
            for (int nt = 0; nt < 2; nt++)
                #pragma unroll
                for (int r = 0; r < 4; r++) acc[mi][np][nt][r] = 0.f;

    #define LOAD8(dst, P, gi, kk)                                             \
    do {                                                                      \
        if (full) {                                                           \
            if (kmode == 2) {                                                 \
                float4 v0 = *(const float4*)&P[gi];                           \
                float4 v1 = *(const float4*)&P[gi + 4];                       \
                dst[0]=v0.x; dst[1]=v0.y; dst[2]=v0.z; dst[3]=v0.w;           \
                dst[4]=v1.x; dst[5]=v1.y; dst[6]=v1.z; dst[7]=v1.w;           \
            } else if (kmode == 1) {                                          \
                _Pragma("unroll")                                             \
                for (int q = 0; q < 4; q++) {                                 \
                    float2 v = *(const float2*)&P[gi + 2 * q];                \
                    dst[2 * q] = v.x; dst[2 * q + 1] = v.y;                   \
                }                                                             \
            } else {                                                          \
                _Pragma("unroll")                                             \
                for (int q = 0; q < 8; q++) dst[q] = P[gi + q];               \
            }                                                                 \
        } else {                                                              \
            _Pragma("unroll")                                                 \
            for (int q = 0; q < 8; q++)                                       \
                dst[q] = (kk + q < k1) ? P[gi + q] : 0.f;                     \
        }                                                                     \
    } while (0)

    // load one 32-k half of chunk IDX into regs
    #define LOAD_HALF(IDX, H)                                                 \
    do {                                                                      \
        const int kb = k0 + (IDX) * CH + (H) * 32;                            \
        const bool full = (kb + 32 <= k1);                                    \
        const int kk = kb + lc * 8;                                           \
        { long gi = (long)(m_base + lr) * K + kk;      LOAD8(aBuf[0], A, gi, kk); } \
        { long gi = (long)(m_base + 64 + lr) * K + kk; LOAD8(aBuf[1], A, gi, kk); } \
        { long gi = (long)lr * K + kk;                 LOAD8(wBuf[0], W, gi, kk); } \
        { long gi = (long)(64 + lr) * K + kk;          LOAD8(wBuf[1], W, gi, kk); } \
    } while (0)

    // store regs into half H of stage at byte offset SO
    #define STS_HALF(SO, H)                                                   \
    do {                                                                      \
        const uint32_t ab = sBase + (SO) + (uint32_t)(H) * HALF_A;            \
        uint32_t hi[4];                                                       \
        uint32_t off0 = swz(lr, lc);                                          \
        uint32_t off1 = swz(64 + lr, lc);                                     \
        cvt8(aBuf[0], hi);  STS128(ab + off0, hi);                            \
        cvt8(aBuf[1], hi);  STS128(ab + off1, hi);                            \
        cvt8(wBuf[0], hi);  STS128(ab + OFS_W + off0, hi);                    \
        cvt8(wBuf[1], hi);  STS128(ab + OFS_W + off1, hi);                    \
    } while (0)

    // mma over half H of stage at byte offset SO (32 k)
    #define MMA_HALF(SO, H)                                                   \
    do {                                                                      \
        const uint32_t so_a = sBase + (SO) + (uint32_t)(H) * HALF_A;          \
        const uint32_t so_w = so_a + OFS_W;                                   \
        _Pragma("unroll")                                                     \
        for (int ks = 0; ks < 2; ks++) {                                      \
            uint32_t AH[2][4];                                                \
            _Pragma("unroll")                                                 \
            for (int mi = 0; mi < 2; mi++) {                                  \
                int r = aR + mi * 16;                                         \
                LDX4(AH[mi], so_a + swz(r, ks * 2 + aCsel));                  \
            }                                                                 \
            _Pragma("unroll")                                                 \
            for (int np = 0; np < 4; np++) {                                  \
                int r = bR + np * 16;                                         \
                uint32_t BH[4];                                               \
                LDX4(BH, so_w + swz(r, ks * 2 + bCsel));                      \
                _Pragma("unroll")                                             \
                for (int mi = 0; mi < 2; mi++) {                              \
                    _Pragma("unroll")                                         \
                    for (int nt = 0; nt < 2; nt++) {                          \
                        MMAF16(acc[mi][np][nt], AH[mi], BH + 2 * nt);         \
                    }                                                         \
                }                                                             \
            }                                                                 \
        }                                                                     \
    } while (0)

    // prologue: chunk 0 into stage 0
    LOAD_HALF(0, 0);
    STS_HALF(0, 0);
    LOAD_HALF(0, 1);
    STS_HALF(0, 1);
    __syncthreads();

    for (int i = 0; i < nchunks; i++) {
        const bool more = (i + 1 < nchunks);
        const uint32_t so  = (uint32_t)(i & 1) * STAGE;
        const uint32_t son = (uint32_t)((i + 1) & 1) * STAGE;

        if (more) LOAD_HALF(i + 1, 0);
        MMA_HALF(so, 0);
        if (more) {
            STS_HALF(son, 0);
            LOAD_HALF(i + 1, 1);
        }
        MMA_HALF(so, 1);
        if (more) STS_HALF(son, 1);
        __syncthreads();
    }

    // epilogue
    #pragma unroll
    for (int mi = 0; mi < 2; mi++) {
        #pragma unroll
        for (int np = 0; np < 4; np++) {
            #pragma unroll
            for (int nt = 0; nt < 2; nt++) {
                int m = m_base + wm * 32 + mi * 16 + (lane >> 2);
                int n = wn * 64 + np * 16 + nt * 8 + (lane & 3) * 2;
                float* o = g_part + ((long)sidx * BATCH + m) * EDIM + n;
                *(float2*)o = make_float2(acc[mi][np][nt][0], acc[mi][np][nt][1]);
                *(float2*)(o + 8 * EDIM) = make_float2(acc[mi][np][nt][2], acc[mi][np][nt][3]);
            }
        }
    }
}

// ================= reduce split-K partials + bias =================
__global__ void reduce_kernel(RedParams p) {
    int g   = blockIdx.y;
    int idx = blockIdx.x * blockDim.x + threadIdx.x;
    int b   = idx >> 7;
    int j   = idx & 127;
    float v = p.bias[g][j];
    int s0 = p.cum[g], s1 = p.cum[g + 1];
    for (int s = s0; s < s1; s++)
        v += g_part[(long)s * (BATCH * EDIM) + idx];
    g_emb[b * NCOLS + p.col_ofs[g] + j] = v;
}

// ================= BN stats (coalesced) =================
__global__ void stats_kernel(const float* g_u, const float* be_u,
                             const float* g_i, const float* be_i) {
    __shared__ float ss[8][32], sq[8][32];
    int lane = threadIdx.x & 31;
    int ty   = threadIdx.x >> 5;
    int c = blockIdx.x * 32 + lane;
    float s = 0.f, q = 0.f;
    for (int b = ty; b < BATCH; b += 8) {
        float x = g_emb[b * NCOLS + c];
        s += x; q += x * x;
    }
    ss[ty][lane] = s; sq[ty][lane] = q;
    __syncthreads();
    if (ty == 0) {
        #pragma unroll
        for (int r = 1; r < 8; r++) { s += ss[r][lane]; q += sq[r][lane]; }
        float mean = s * (1.f / BATCH);
        float var  = q * (1.f / BATCH) - mean * mean;
        float gamma = (c < 256) ? g_u[c]  : g_i[c - 256];
        float beta  = (c < 256) ? be_u[c] : be_i[c - 256];
        float sc = gamma * rsqrtf(var + EPS);
        g_scale[c] = sc;
        g_shift[c] = beta - mean * sc;
    }
}

// ================= tower layer 1: j-split, grid 256 (R14) =================
// CTA: 8 rows x 64 output cols. warp = 1 row, 2 cols per lane.
#define WS_PITCH 66
__global__ __launch_bounds__(256) void tower1_kernel(TowerParams p) {
    __shared__ float As[8 * 384];
    __shared__ float Ws[2][32 * WS_PITCH];

    int which = blockIdx.x >> 7;          // 0 = user, 1 = item
    int rest  = blockIdx.x & 127;
    int blk   = rest >> 1;                // 0..63 row block
    int jh    = rest & 1;                 // 0/1 col half
    int K     = which ? 384 : 256;
    int a_ofs = which ? 256 : 0;
    int jbase = jh * 64;
    const float* __restrict__ W    = p.W[which];
    const float* __restrict__ bias = p.bias[which];
    float* C = which ? g_hi_ : g_hu;

    int t    = threadIdx.x;
    int lane = t & 31;
    int w    = t >> 5;
    int m0   = blk * 8;

    const int jw = t >> 2;        // 0..63 (local j)
    const int kh = (t & 3) * 8;   // 0,8,16,24
    const int ntiles = K / 32;

    float wreg[8];
    // prefetch W tile 0 (hide under As gather)
    {
        const float* wr = &W[(jbase + jw) * K + kh];
        float4 v0 = *(const float4*)&wr[0];
        float4 v1 = *(const float4*)&wr[4];
        wreg[0]=v0.x; wreg[1]=v0.y; wreg[2]=v0.z; wreg[3]=v0.w;
        wreg[4]=v1.x; wreg[5]=v1.y; wreg[6]=v1.z; wreg[7]=v1.w;
    }

    for (int e = t; e < 8 * K; e += 256) {
        int r = e / K, c = e - r * K;
        float v = g_emb[(m0 + r) * NCOLS + a_ofs + c];
        As[e] = fmaf(v, g_scale[a_ofs + c], g_shift[a_ofs + c]);
    }

    #pragma unroll
    for (int q = 0; q < 8; q++) Ws[0][(kh + q) * WS_PITCH + jw] = wreg[q];
    __syncthreads();

    const int r = w;              // warp = row
    float acc[2];
    acc[0] = bias[jbase + lane * 2];
    acc[1] = bias[jbase + lane * 2 + 1];

    for (int i = 0; i < ntiles; i++) {
        const bool more = (i + 1 < ntiles);
        if (more) {
            const float* wr = &W[(jbase + jw) * K + (i + 1) * 32 + kh];
            float4 v0 = *(const float4*)&wr[0];
            float4 v1 = *(const float4*)&wr[4];
            wreg[0]=v0.x; wreg[1]=v0.y; wreg[2]=v0.z; wreg[3]=v0.w;
            wreg[4]=v1.x; wreg[5]=v1.y; wreg[6]=v1.z; wreg[7]=v1.w;
        }
        const float* wsb = Ws[i & 1];
        const int kb = i * 32;
        #pragma unroll 8
        for (int kk = 0; kk < 32; kk++) {
            float a = As[r * K + kb + kk];
            float2 wv = *(const float2*)&wsb[kk * WS_PITCH + lane * 2];
            acc[0] = fmaf(a, wv.x, acc[0]);
            acc[1] = fmaf(a, wv.y, acc[1]);
        }
        if (more) {
            #pragma unroll
            for (int q = 0; q < 8; q++)
                Ws[(i + 1) & 1][(kh + q) * WS_PITCH + jw] = wreg[q];
            __syncthreads();
        }
    }

    float2 v;
    v.x = fmaxf(acc[0], 0.f);
    v.y = fmaxf(acc[1], 0.f);
    *(float2*)&C[(m0 + r) * EDIM + jbase + lane * 2] = v;
}

// ================= tower layer 2 (user + item), W double-buffered =====
__global__ __launch_bounds__(256) void tower2_kernel(TowerParams p) {
    __shared__ float As[8 * 128];
    __shared__ float Ws[2][32 * 128];

    int which = blockIdx.x >> 6;
    int blk   = blockIdx.x & 63;
    const int K = 128;
    const float* __restrict__ A    = which ? g_hi_ : g_hu;
    const float* __restrict__ W    = p.W[which];
    const float* __restrict__ bias = p.bias[which];
    float* C = which ? g_ie : g_ue;

    int t  = threadIdx.x;
    int m0 = blk * 8;

    for (int e = t; e < 8 * K; e += 256) As[e] = A[m0 * K + e];

    int r  = t >> 5;
    int j0 = (t & 31) * 4;
    float acc[4];
    #pragma unroll
    for (int j = 0; j < 4; j++) acc[j] = bias[j0 + j];

    const int jw = t >> 1;
    const int kh = (t & 1) * 16;
    const int ntiles = K / 32;

    float wreg[16];
    #pragma unroll
    for (int q = 0; q < 4; q++) {
        float4 v = *(const float4*)&W[jw * K + kh + q * 4];
        wreg[q * 4 + 0] = v.x; wreg[q * 4 + 1] = v.y;
        wreg[q * 4 + 2] = v.z; wreg[q * 4 + 3] = v.w;
    }
    #pragma unroll
    for (int q = 0; q < 16; q++) Ws[0][(kh + q) * 128 + jw] = wreg[q];
    __syncthreads();

    for (int i = 0; i < ntiles; i++) {
        const bool more = (i + 1 < ntiles);
        if (more) {
            int kb = (i + 1) * 32;
            #pragma unroll
            for (int q = 0; q < 4; q++) {
                float4 v = *(const float4*)&W[jw * K + kb + kh + q * 4];
                wreg[q * 4 + 0] = v.x; wreg[q * 4 + 1] = v.y;
                wreg[q * 4 + 2] = v.z; wreg[q * 4 + 3] = v.w;
            }
        }
        const float* wsb = Ws[i & 1];
        const int kb = i * 32;
        #pragma unroll 8
        for (int kk = 0; kk < 32; kk++) {
            float a = As[r * K + kb + kk];
            float4 wv = *(const float4*)&wsb[kk * 128 + j0];
            acc[0] = fmaf(a, wv.x, acc[0]);
            acc[1] = fmaf(a, wv.y, acc[1]);
            acc[2] = fmaf(a, wv.z, acc[2]);
            acc[3] = fmaf(a, wv.w, acc[3]);
        }
        if (more) {
            #pragma unroll
            for (int q = 0; q < 16; q++)
                Ws[(i + 1) & 1][(kh + q) * 128 + jw] = wreg[q];
            __syncthreads();
        }
    }

    *(float4*)&C[(m0 + r) * EDIM + j0] =
        make_float4(acc[0], acc[1], acc[2], acc[3]);
}

// ================= final dot =================
__global__ void dot_kernel(float* __restrict__ out) {
    int warp = threadIdx.x >> 5;
    int lane = threadIdx.x & 31;
    int b = blockIdx.x * 8 + warp;
    float s = 0.f;
    #pragma unroll
    for (int j = lane; j < EDIM; j += 32)
        s += g_ue[b * EDIM + j] * g_ie[b * EDIM + j];
    #pragma unroll
    for (int o = 16; o > 0; o >>= 1)
        s += __shfl_xor_sync(0xffffffffu, s, o);
    if (lane == 0) out[b] = s;
}

// ================= launch =================
extern "C" void kernel_launch(void* const* d_in, const int* in_sizes, int n_in,
                              void* d_out, int out_size) {
    const float* kw   = (const float*)d_in[0];
    const float* fo   = (const float*)d_in[1];
    const float* au   = (const float*)d_in[2];
    const float* mg   = (const float*)d_in[3];
    const float* tg   = (const float*)d_in[4];
    const float* W_kw = (const float*)d_in[5];
    const float* b_kw = (const float*)d_in[6];
    const float* W_au = (const float*)d_in[7];
    const float* b_au = (const float*)d_in[8];
    const float* W_mg = (const float*)d_in[9];
    const float* b_mg = (const float*)d_in[10];
    const float* W_tg = (const float*)d_in[11];
    const float* b_tg = (const float*)d_in[12];
    const float* g_u  = (const float*)d_in[13];
    const float* be_u = (const float*)d_in[14];
    const float* W_u1 = (const float*)d_in[15];
    const float* b_u1 = (const float*)d_in[16];
    const float* W_u2 = (const float*)d_in[17];
    const float* b_u2 = (const float*)d_in[18];
    const float* g_i  = (const float*)d_in[19];
    const float* be_i = (const float*)d_in[20];
    const float* W_i1 = (const float*)d_in[21];
    const float* b_i1 = (const float*)d_in[22];
    const float* W_i2 = (const float*)d_in[23];
    const float* b_i2 = (const float*)d_in[24];

    const int KW = 372226, AU = 19065, MG = 28028, TG = 86037;

    BigParams bp;
    bp.A[0] = kw;  bp.A[1] = fo;  bp.A[2] = au;  bp.A[3] = mg;  bp.A[4] = tg;
    bp.W[0] = W_kw; bp.W[1] = W_au; bp.W[2] = W_au; bp.W[3] = W_mg; bp.W[4] = W_tg;
    bp.K[0] = KW;  bp.K[1] = AU;  bp.K[2] = AU;  bp.K[3] = MG;  bp.K[4] = TG;
    // K per slice (multiple of 64), count*kc >= K  (R13 values)
    bp.kc[0] = 7168;   // 52*7168 = 372736
    bp.kc[1] = 6400;
    bp.kc[2] = 6400;
    bp.kc[3] = 7040;
    bp.kc[4] = 7232;
    bp.cum[0] = 0;
    bp.cum[1] = NSL_KW;
    bp.cum[2] = NSL_KW + NSL_FO;
    bp.cum[3] = NSL_KW + NSL_FO + NSL_AU;
    bp.cum[4] = NSL_KW + NSL_FO + NSL_AU + NSL_MG;
    bp.cum[5] = NSL_TOT;

    RedParams rp;
    rp.bias[0] = b_kw; rp.bias[1] = b_au; rp.bias[2] = b_au;
    rp.bias[3] = b_mg; rp.bias[4] = b_tg;
    for (int i = 0; i < 6; i++) rp.cum[i] = bp.cum[i];
    rp.col_ofs[0] = 0;   rp.col_ofs[1] = 128; rp.col_ofs[2] = 256;
    rp.col_ofs[3] = 384; rp.col_ofs[4] = 512;

    TowerParams t1;
    t1.W[0] = W_u1; t1.W[1] = W_i1;
    t1.bias[0] = b_u1; t1.bias[1] = b_i1;
    TowerParams t2;
    t2.W[0] = W_u2; t2.W[1] = W_i2;
    t2.bias[0] = b_u2; t2.bias[1] = b_i2;

    cudaFuncSetAttribute(big_gemm_kernel,
                         cudaFuncAttributeMaxDynamicSharedMemorySize, SMEM_DYN);

    big_gemm_kernel<<<NSL_TOT * 4, 256, SMEM_DYN>>>(bp);
    reduce_kernel<<<dim3((BATCH * EDIM) / 256, 5), 256>>>(rp);
    stats_kernel<<<NCOLS / 32, 256>>>(g_u, be_u, g_i, be_i);
    tower1_kernel<<<256, 256>>>(t1);
    tower2_kernel<<<128, 256>>>(t2);
    dot_kernel<<<BATCH / 8, 256>>>((float*)d_out);
}